// round 14
// baseline (speedup 1.0000x reference)
#include <cuda_runtime.h>
#include <math.h>

#define TT   1460
#define TTP  1470            // padded scratch time (49 * 30)
#define GG   5000
#define TS   30              // timesteps per smem tile
#define NT   49              // 1470 / 30
#define CH   15              // UH length
#define CPW  3               // cells per warp (lanes duplicate lane%3)
#define WPB  4               // warps per block -> one per SMSP
#define CPB  12              // cells per block
#define RW   9               // floats per row per warp (CPW * 3)
#define NSL  14              // conv t-slices
#define SLEN 105             // steps per conv slice (7 * 15)

// scratch: (ht0, ht1) per (t, g), time-padded -- 58.8 MB
__device__ float2 g_scr[(size_t)TTP * GG];

// ---- packed f32x2 + approx transcendental helpers -----------------------------
#define PACK2(d, lo, hi)   asm("mov.b64 %0, {%1, %2};" : "=l"(d) : "f"(lo), "f"(hi))
#define UNPACK2(lo, hi, d) asm("mov.b64 {%0, %1}, %2;" : "=f"(lo), "=f"(hi) : "l"(d))
#define FMA2(d, a, b, c)   asm("fma.rn.f32x2 %0, %1, %2, %3;" : "=l"(d) : "l"(a), "l"(b), "l"(c))

__device__ __forceinline__ float lg2a(float x) { float r; asm("lg2.approx.f32 %0, %1;" : "=f"(r) : "f"(x)); return r; }
__device__ __forceinline__ float ex2a(float x) { float r; asm("ex2.approx.f32 %0, %1;" : "=f"(r) : "f"(x)); return r; }

__device__ __forceinline__ void cp_async4(void* sm, const void* gm) {
    unsigned a = (unsigned)__cvta_generic_to_shared(sm);
    asm volatile("cp.async.ca.shared.global [%0], [%1], 4;\n" :: "r"(a), "l"(gm));
}
__device__ __forceinline__ void cp_commit() { asm volatile("cp.async.commit_group;\n" ::: "memory"); }
__device__ __forceinline__ void cp_wait1()  { asm volatile("cp.async.wait_group 1;\n" ::: "memory"); }
__device__ __forceinline__ void cp_wait0()  { asm volatile("cp.async.wait_group 0;\n" ::: "memory"); }

// ============== Kernel A: warp-spread scan (spine only, CPW=3) ==================
__global__ __launch_bounds__(128, 3)
void hmets_scan(const float* __restrict__ x,
                const float* __restrict__ par,
                float* __restrict__ out)
{
    __shared__ float smAll[WPB][2][TS * RW];   // 8640 B

    const int tid  = threadIdx.x;
    const int wid  = tid >> 5;
    const int lane = tid & 31;
    const int li   = lane % 3;                    // cell slot within warp
    const int gw0  = blockIdx.x * CPB + wid * CPW;
    const int g    = gw0 + li;
    const bool cact = (g < GG);                   // per-cell activity

    float (*smw)[TS * RW] = smAll[wid];

    // -------- per-cell physical parameters (last timestep row only) -----------------
    const int gcl = cact ? g : (GG - 1);
    const float* pr = par + ((size_t)(TT - 1) * GG + gcl) * 20;
    float s[16];
#pragma unroll
    for (int i = 0; i < 16; i++) {
        float v = __ldg(pr + i);
        s[i] = 1.0f / (1.0f + expf(-v));
    }
    const float ddf_min = 20.0f * s[0];
    const float ddf_sum = ddf_min + 20.0f * s[1];
    const float Tbm     = -2.0f + 5.0f * s[2];
    const float Kcum    = 0.01f + 0.19f * s[3];
    const float fcmin   = 0.1f * s[4];
    const float fc_sum  = fcmin + 0.01f + 0.24f * s[5];
    const float Ccum    = 0.005f + 0.045f * s[6];
    const float Tbf     = -5.0f + 7.0f * s[7];
    const float Kf      = 5.0f * s[8];
    const float efe     = s[9];
    const float ETe     = 3.0f * s[10];
    const float cRun    = s[11];
    const float cV2P    = 1e-5f + (0.02f - 1e-5f) * s[12];
    const float cVad    = 0.1f * s[13];
    const float cPh     = 1e-5f + (0.01f - 1e-5f) * s[14];
    const float Vmax    = 0.001f + (500.0f - 0.001f) * s[15];
    const float invVmax = 1.0f / Vmax;
    const float dmK   = ddf_min * Kcum;       // ddf = fma(dmK, C, ddf_min)
    const float fcC   = fc_sum * Ccum;        // wrf = fma(-fcC, C, fc_sum)
    const float cVb   = 1.0f - cVad - cV2P;   // V1 = fma(cVb, V, infil) - ht1
    const float lKf   = lg2a(Kf);             // potf = ex2(fma(efe, lg2(base), lKf))
    const float omPh  = 1.0f - cPh;           // P' = (P + v2p) * (1 - cPh)

    // -------- per-warp tile prefetch (4B cp.async, zero-padded) ---------------------
    auto prefetch = [&](int k) {
        float* dst = smw[k & 1];
        int t0 = k * TS;
        for (int j = lane; j < TS * RW; j += 32) {
            int row = j / RW, c = j - row * RW;
            int cell = gw0 + c / 3;
            if (cell < GG && (t0 + row) < TT) {
                const float* gp = x + (size_t)(t0 + row) * (GG * 3) + gw0 * 3 + c;
                cp_async4(dst + row * RW + c, gp);
            } else {
                dst[row * RW + c] = 0.0f;
            }
        }
        cp_commit();
    };

    // -------- state -----------------------------------------------------------------
    float S = 1e-5f, W = 1e-5f, C = 1e-5f, P = 1e-5f;
    float V = 0.5f * Vmax;

    const bool wr_act = cact && (lane < CPW);
    float2* sp = g_scr + (cact ? g : 0);      // predicated store; safe base
    float*  op = out + (cact ? g : 0);

    prefetch(0);
    for (int k = 0; k < NT; k++) {
        const int t0 = k * TS;
        if (k + 1 < NT) { prefetch(k + 1); cp_wait1(); }
        else            { cp_wait0(); }
        __syncwarp();
        const float* sb = smw[k & 1];

#pragma unroll 1
        for (int c2 = 0; c2 < 2; c2++) {
            const float* rb = sb + c2 * CH * RW + li * 3;
            const int tb = t0 + c2 * CH;
#pragma unroll
            for (int u = 0; u < CH; u++) {
                float Pp = rb[u * RW + 0];
                float Tt = rb[u * RW + 1];
                float PE = rb[u * RW + 2];

                // forcing-derived (off the state recurrence)
                float rain = (Tt >= 0.0f) ? Pp : 0.0f;
                float snow = Pp - rain;
                float base = fmaxf(Tbf - Tt, 1e-5f);
                float potf = ex2a(fmaf(efe, lg2a(base), lKf));
                float dtp  = fmaxf(Tt - Tbm, 0.0f);
                float RET  = ETe * PE;

                // snowpack
                float fr = fminf(potf, W);
                W -= fr;
                S += fr;
                float ddf  = fminf(fmaf(dmK, C, ddf_min), ddf_sum);
                float S1   = S + snow;
                float melt = fminf(ddf * dtp, S1);
                S = S1 - melt;
                float Ct = C + melt;
                C = (S > 1e-5f) ? Ct : 0.0f;

                // retention (select -> min identity, exact)
                float wrf  = fmaxf(fmaf(-fcC, C, fc_sum), fcmin);
                float wr   = wrf * S;
                float wtmp = (W + rain) + melt;
                float wa   = fmaxf(wtmp - wr, 0.0f);
                W = fminf(wtmp, wr);

                // vadose / phreatic (overflow clamp -> min identity, exact)
                float ratio = V * invVmax;
                float cr    = cRun * ratio;
                float cr2   = cr * ratio;
                float ht0   = cr * wa;
                float infil = fmaxf((wa - RET) - ht0, 0.0f);
                float ht1   = cr2 * infil;
                float v2p   = cV2P * V;
                float V1    = fmaf(cVb, V, infil) - ht1;
                float Vn    = fminf(V1, Vmax);
                float gwV   = cVad * V;              // ht2 from OLD V
                V = Vn;
                ht1 += V1 - Vn;
                float Pp1 = P + v2p;
                float ht3 = cPh * Pp1;
                P = Pp1 * omPh;
                float gw  = gwV + ht3;

                // stores: scratch unguarded in time (padded), out guarded
                float2 h2; h2.x = ht0; h2.y = ht1;
                if (wr_act) *sp = h2;
                sp += GG;
                if (wr_act && (tb + u) < TT) *op = gw;
                op += GG;
            }
        }
        __syncwarp();
    }
}

// ============== Kernel B: dual gamma-UH conv (RMW into out) =====================
__global__ __launch_bounds__(32, 16)
void hmets_conv(const float* __restrict__ par,
                float* __restrict__ out)
{
    const int lane = threadIdx.x;
    const int g    = blockIdx.x * 32 + lane;
    if (g >= GG) return;
    const int t0   = blockIdx.y * SLEN;

    // routing params (sigmoid of last row, cols 16..19)
    const float* pr = par + ((size_t)(TT - 1) * GG + g) * 20 + 16;
    float a1 = 0.3f  + (20.0f - 0.3f)  / (1.0f + expf(-__ldg(pr + 0)));
    float b1 = 0.01f + (5.0f  - 0.01f) / (1.0f + expf(-__ldg(pr + 1)));
    float a2 = 0.5f  + (13.0f - 0.5f)  / (1.0f + expf(-__ldg(pr + 2)));
    float b2 = 0.15f + (1.5f  - 0.15f) / (1.0f + expf(-__ldg(pr + 3)));

    unsigned long long uhp[CH];
    {
        const float L2E = 1.44269504f;
        float i1 = L2E / b1, i2 = L2E / b2;
        float w1[CH], w2[CH];
        float n1 = 0.f, n2 = 0.f;
#pragma unroll
        for (int l = 0; l < CH; l++) {
            float t  = (float)l + 0.5f;
            float lt = lg2a(t);
            w1[l] = ex2a(fmaf(a1 - 1.0f, lt, -t * i1));
            w2[l] = ex2a(fmaf(a2 - 1.0f, lt, -t * i2));
            n1 += w1[l]; n2 += w2[l];
        }
        n1 = 1.0f / n1; n2 = 1.0f / n2;
#pragma unroll
        for (int l = 0; l < CH; l++) PACK2(uhp[l], w1[l] * n1, w2[l] * n2);
    }

    // ring preload: slot j holds h[t0 - 15 + j]
    unsigned long long hpk[CH];
    hpk[0] = 0ull;
#pragma unroll
    for (int j = 1; j < CH; j++) {
        int t = t0 - CH + j;
        if (t >= 0) {
            float2 h = __ldg(&g_scr[(size_t)t * GG + g]);
            PACK2(hpk[j], h.x, h.y);
        } else hpk[j] = 0ull;
    }

#pragma unroll 1
    for (int cb = 0; cb < SLEN / CH; cb++) {
        const int tb = t0 + cb * CH;
        if (tb >= TT) break;

        // batch-load 15 history rows + 15 gw partials (MLP)
        float2 hv[CH];
        float  gv[CH];
#pragma unroll
        for (int u = 0; u < CH; u++) {
            int t = tb + u;
            if (t < TT) {
                hv[u] = __ldg(&g_scr[(size_t)t * GG + g]);
                gv[u] = out[(size_t)t * GG + g];
            } else {
                hv[u] = make_float2(0.f, 0.f);
                gv[u] = 0.f;
            }
        }
#pragma unroll
        for (int u = 0; u < CH; u++) {
            PACK2(hpk[u], hv[u].x, hv[u].y);
            unsigned long long qp = 0ull;
#pragma unroll
            for (int l = 0; l < CH; l++)
                FMA2(qp, uhp[l], hpk[(u - l + CH) % CH], qp);
            float qlo, qhi;
            UNPACK2(qlo, qhi, qp);
            if (tb + u < TT)
                out[(size_t)(tb + u) * GG + g] = gv[u] + qlo + qhi;
        }
    }
}

extern "C" void kernel_launch(void* const* d_in, const int* in_sizes, int n_in,
                              void* d_out, int out_size)
{
    (void)in_sizes; (void)n_in; (void)out_size;
    const float* x   = (const float*)d_in[0];   // x_phy  [1460, 5000, 3]
    const float* par = (const float*)d_in[1];   // params [1460, 5000, 20]
    float* out = (float*)d_out;                 // Q      [1460, 5000]

    hmets_scan<<<(GG + CPB - 1) / CPB, WPB * 32>>>(x, par, out);
    dim3 cg((GG + 31) / 32, NSL);
    hmets_conv<<<cg, 32>>>(par, out);
}

// round 15
// speedup vs baseline: 1.1034x; 1.1034x over previous
#include <cuda_runtime.h>
#include <math.h>

#define TT   1460
#define TTP  1470            // padded scratch time (49 * 30)
#define GG   5000
#define TS   30              // timesteps per smem tile
#define NT   49              // 1470 / 30
#define CH   15              // UH length
#define CPW  3               // cells per warp (lanes duplicate lane%3)
#define WPB  4               // warps per block
#define CPB  12              // cells per block
#define BRW  36              // floats per block row (CPB * 3), 144 B, 16B-aligned
#define NSL  14              // conv t-slices
#define SLEN 105             // steps per conv slice (7 * 15)

// scratch: (ht0, ht1) per (t, g), time-padded -- 58.8 MB
__device__ float2 g_scr[(size_t)TTP * GG];

// ---- packed f32x2 + approx transcendental helpers -----------------------------
#define PACK2(d, lo, hi)   asm("mov.b64 %0, {%1, %2};" : "=l"(d) : "f"(lo), "f"(hi))
#define UNPACK2(lo, hi, d) asm("mov.b64 {%0, %1}, %2;" : "=f"(lo), "=f"(hi) : "l"(d))
#define FMA2(d, a, b, c)   asm("fma.rn.f32x2 %0, %1, %2, %3;" : "=l"(d) : "l"(a), "l"(b), "l"(c))

__device__ __forceinline__ float lg2a(float x) { float r; asm("lg2.approx.f32 %0, %1;" : "=f"(r) : "f"(x)); return r; }
__device__ __forceinline__ float ex2a(float x) { float r; asm("ex2.approx.f32 %0, %1;" : "=f"(r) : "f"(x)); return r; }

__device__ __forceinline__ void cp_async16(void* sm, const void* gm) {
    unsigned a = (unsigned)__cvta_generic_to_shared(sm);
    asm volatile("cp.async.cg.shared.global [%0], [%1], 16;\n" :: "r"(a), "l"(gm));
}
__device__ __forceinline__ void cp_commit() { asm volatile("cp.async.commit_group;\n" ::: "memory"); }
__device__ __forceinline__ void cp_wait1()  { asm volatile("cp.async.wait_group 1;\n" ::: "memory"); }
__device__ __forceinline__ void cp_wait0()  { asm volatile("cp.async.wait_group 0;\n" ::: "memory"); }

// ====== Kernel A: warp-spread scan, CPW=3, block-cooperative 16B prefetch =======
__global__ __launch_bounds__(128, 3)
void hmets_scan(const float* __restrict__ x,
                const float* __restrict__ par,
                float* __restrict__ out)
{
    __shared__ __align__(16) float smb[2][TS * BRW];   // 8640 B, block-shared

    const int tid  = threadIdx.x;
    const int wid  = tid >> 5;
    const int lane = tid & 31;
    const int li   = lane % 3;                    // cell slot within warp
    const int gb0  = blockIdx.x * CPB;            // block cell base
    const int g    = gb0 + wid * CPW + li;
    const bool cact = (g < GG);

    // valid floats per block row (multiple of 4: 36 or 24)
    const int nval = (GG - gb0 >= CPB ? CPB : (GG - gb0)) * 3;

    // -------- per-cell physical parameters (last timestep row only) -----------------
    const int gcl = cact ? g : (GG - 1);
    const float* pr = par + ((size_t)(TT - 1) * GG + gcl) * 20;
    float s[16];
#pragma unroll
    for (int i = 0; i < 16; i++) {
        float v = __ldg(pr + i);
        s[i] = 1.0f / (1.0f + expf(-v));
    }
    const float ddf_min = 20.0f * s[0];
    const float ddf_sum = ddf_min + 20.0f * s[1];
    const float Tbm     = -2.0f + 5.0f * s[2];
    const float Kcum    = 0.01f + 0.19f * s[3];
    const float fcmin   = 0.1f * s[4];
    const float fc_sum  = fcmin + 0.01f + 0.24f * s[5];
    const float Ccum    = 0.005f + 0.045f * s[6];
    const float Tbf     = -5.0f + 7.0f * s[7];
    const float Kf      = 5.0f * s[8];
    const float efe     = s[9];
    const float ETe     = 3.0f * s[10];
    const float cRun    = s[11];
    const float cV2P    = 1e-5f + (0.02f - 1e-5f) * s[12];
    const float cVad    = 0.1f * s[13];
    const float cPh     = 1e-5f + (0.01f - 1e-5f) * s[14];
    const float Vmax    = 0.001f + (500.0f - 0.001f) * s[15];
    const float invVmax = 1.0f / Vmax;
    const float dmK   = ddf_min * Kcum;
    const float fcC   = fc_sum * Ccum;
    const float cVb   = 1.0f - cVad - cV2P;
    const float lKf   = lg2a(Kf);
    const float omPh  = 1.0f - cPh;

    // -------- block-cooperative prefetch: 270 float4 per tile, 16B-aligned ----------
    auto prefetch = [&](int k) {
        float* dst = smb[k & 1];
        int t0 = k * TS;
        for (int j = tid; j < TS * 9; j += 128) {      // 9 float4 per block row
            int row = j / 9, c4 = (j - row * 9) * 4;   // c4 = float offset in row
            if ((t0 + row) < TT && (c4 + 4) <= nval) {
                const float* gp = x + (size_t)(t0 + row) * (GG * 3) + gb0 * 3 + c4;
                cp_async16(dst + row * BRW + c4, gp);
            } else {
                float4 z = {0.f, 0.f, 0.f, 0.f};
                *(float4*)(dst + row * BRW + c4) = z;
            }
        }
        cp_commit();
    };

    // -------- state -----------------------------------------------------------------
    float S = 1e-5f, W = 1e-5f, C = 1e-5f, P = 1e-5f;
    float V = 0.5f * Vmax;

    const bool wr_act = cact && (lane < CPW);
    float2* sp = g_scr + (cact ? g : 0);
    float*  op = out + (cact ? g : 0);

    prefetch(0);
    for (int k = 0; k < NT; k++) {
        const int t0 = k * TS;
        if (k + 1 < NT) { prefetch(k + 1); cp_wait1(); }
        else            { cp_wait0(); }
        __syncthreads();                                // data from all threads visible
        const float* sb = smb[k & 1];
        const float* rbw = sb + wid * (CPW * 3) + li * 3;

#pragma unroll 1
        for (int c2 = 0; c2 < 2; c2++) {
            const float* rb = rbw + c2 * CH * BRW;
            const int tb = t0 + c2 * CH;
#pragma unroll
            for (int u = 0; u < CH; u++) {
                float Pp = rb[u * BRW + 0];
                float Tt = rb[u * BRW + 1];
                float PE = rb[u * BRW + 2];

                // forcing-derived (off the state recurrence)
                float rain = (Tt >= 0.0f) ? Pp : 0.0f;
                float snow = (Tt >= 0.0f) ? 0.0f : Pp;
                float base = fmaxf(Tbf - Tt, 1e-5f);
                float potf = ex2a(fmaf(efe, lg2a(base), lKf));
                float dtp  = fmaxf(Tt - Tbm, 0.0f);
                float RET  = ETe * PE;

                // snowpack
                float fr = fminf(potf, W);
                W -= fr;
                S += fr;
                float ddf  = fminf(fmaf(dmK, C, ddf_min), ddf_sum);
                float S1   = S + snow;
                float melt = fminf(ddf * dtp, S1);
                S = S1 - melt;
                float Ct = C + melt;
                C = (S > 1e-5f) ? Ct : 0.0f;

                // retention (select -> min identity, exact)
                float wrf  = fmaxf(fmaf(-fcC, C, fc_sum), fcmin);
                float wr   = wrf * S;
                float wtmp = (W + rain) + melt;
                float wa   = fmaxf(wtmp - wr, 0.0f);
                W = fminf(wtmp, wr);

                // vadose / phreatic (overflow clamp -> min identity, exact)
                float ratio = V * invVmax;
                float cr    = cRun * ratio;
                float cr2   = cr * ratio;
                float ht0   = cr * wa;
                float infil = fmaxf((wa - RET) - ht0, 0.0f);
                float ht1   = cr2 * infil;
                float v2p   = cV2P * V;
                float V1    = fmaf(cVb, V, infil) - ht1;
                float Vn    = fminf(V1, Vmax);
                float gwV   = cVad * V;              // ht2 from OLD V
                V = Vn;
                ht1 += V1 - Vn;
                float Pp1 = P + v2p;
                float ht3 = cPh * Pp1;
                P = Pp1 * omPh;
                float gw  = gwV + ht3;

                float2 h2; h2.x = ht0; h2.y = ht1;
                if (wr_act) *sp = h2;
                sp += GG;
                if (wr_act && (tb + u) < TT) *op = gw;
                op += GG;
            }
        }
        __syncthreads();                                // all warps done before refill
    }
}

// ============== Kernel B: dual gamma-UH conv (RMW into out) =====================
__global__ __launch_bounds__(32, 16)
void hmets_conv(const float* __restrict__ par,
                float* __restrict__ out)
{
    const int lane = threadIdx.x;
    const int g    = blockIdx.x * 32 + lane;
    if (g >= GG) return;
    const int t0   = blockIdx.y * SLEN;

    const float* pr = par + ((size_t)(TT - 1) * GG + g) * 20 + 16;
    float a1 = 0.3f  + (20.0f - 0.3f)  / (1.0f + expf(-__ldg(pr + 0)));
    float b1 = 0.01f + (5.0f  - 0.01f) / (1.0f + expf(-__ldg(pr + 1)));
    float a2 = 0.5f  + (13.0f - 0.5f)  / (1.0f + expf(-__ldg(pr + 2)));
    float b2 = 0.15f + (1.5f  - 0.15f) / (1.0f + expf(-__ldg(pr + 3)));

    unsigned long long uhp[CH];
    {
        const float L2E = 1.44269504f;
        float i1 = L2E / b1, i2 = L2E / b2;
        float w1[CH], w2[CH];
        float n1 = 0.f, n2 = 0.f;
#pragma unroll
        for (int l = 0; l < CH; l++) {
            float t  = (float)l + 0.5f;
            float lt = lg2a(t);
            w1[l] = ex2a(fmaf(a1 - 1.0f, lt, -t * i1));
            w2[l] = ex2a(fmaf(a2 - 1.0f, lt, -t * i2));
            n1 += w1[l]; n2 += w2[l];
        }
        n1 = 1.0f / n1; n2 = 1.0f / n2;
#pragma unroll
        for (int l = 0; l < CH; l++) PACK2(uhp[l], w1[l] * n1, w2[l] * n2);
    }

    unsigned long long hpk[CH];
    hpk[0] = 0ull;
#pragma unroll
    for (int j = 1; j < CH; j++) {
        int t = t0 - CH + j;
        if (t >= 0) {
            float2 h = __ldg(&g_scr[(size_t)t * GG + g]);
            PACK2(hpk[j], h.x, h.y);
        } else hpk[j] = 0ull;
    }

#pragma unroll 1
    for (int cb = 0; cb < SLEN / CH; cb++) {
        const int tb = t0 + cb * CH;
        if (tb >= TT) break;

        float2 hv[CH];
        float  gv[CH];
#pragma unroll
        for (int u = 0; u < CH; u++) {
            int t = tb + u;
            if (t < TT) {
                hv[u] = __ldg(&g_scr[(size_t)t * GG + g]);
                gv[u] = out[(size_t)t * GG + g];
            } else {
                hv[u] = make_float2(0.f, 0.f);
                gv[u] = 0.f;
            }
        }
#pragma unroll
        for (int u = 0; u < CH; u++) {
            PACK2(hpk[u], hv[u].x, hv[u].y);
            unsigned long long qp = 0ull;
#pragma unroll
            for (int l = 0; l < CH; l++)
                FMA2(qp, uhp[l], hpk[(u - l + CH) % CH], qp);
            float qlo, qhi;
            UNPACK2(qlo, qhi, qp);
            if (tb + u < TT)
                out[(size_t)(tb + u) * GG + g] = gv[u] + qlo + qhi;
        }
    }
}

extern "C" void kernel_launch(void* const* d_in, const int* in_sizes, int n_in,
                              void* d_out, int out_size)
{
    (void)in_sizes; (void)n_in; (void)out_size;
    const float* x   = (const float*)d_in[0];   // x_phy  [1460, 5000, 3]
    const float* par = (const float*)d_in[1];   // params [1460, 5000, 20]
    float* out = (float*)d_out;                 // Q      [1460, 5000]

    hmets_scan<<<(GG + CPB - 1) / CPB, WPB * 32>>>(x, par, out);
    dim3 cg((GG + 31) / 32, NSL);
    hmets_conv<<<cg, 32>>>(par, out);
}